// round 4
// baseline (speedup 1.0000x reference)
#include <cuda_runtime.h>
#include <cuda_bf16.h>
#include <cstdint>

// Problem constants (fixed by the reference)
#define T_ 4096
#define B_ 8
#define F_ 512
#define H_ 1024

#define TM 128   // T-tile (m)
#define TN 128   // H-chunk tile (n)
#define TK 16    // k-step

// smem strides in uint16 units (padded for conflict-free ldmatrix)
#define A_STRIDE 24        // 16 k + 8 pad  -> 48B row stride
#define B_STRIDE 136       // 128 n + 8 pad -> 272B row stride
#define A_ELEMS (TM * A_STRIDE)   // 3072 u16 per part
#define B_ELEMS (TK * B_STRIDE)   // 2176 u16 per part

__device__ __forceinline__ float fix_nan(float v) {
    unsigned u = __float_as_uint(v) & 0x7fffffffu;
    return (u > 0x7f800000u) ? 0.0f : v;
}

__device__ __forceinline__ float bfr(float v) {            // round-to-nearest bf16, back to f32
    return __bfloat162float(__float2bfloat16(v));
}

__device__ __forceinline__ uint32_t f2bf2(float lo, float hi) {  // pack: low half = 'lo'
    uint32_t r;
    asm("cvt.rn.bf16x2.f32 %0, %1, %2;" : "=r"(r) : "f"(hi), "f"(lo));
    return r;
}

__device__ __forceinline__ uint32_t smem_u32(const void* p) {
    uint32_t r;
    asm("{ .reg .u64 t; cvta.to.shared.u64 t, %1; cvt.u32.u64 %0, t; }" : "=r"(r) : "l"(p));
    return r;
}

__device__ __forceinline__ void ldsm4(uint32_t r[4], uint32_t addr) {
    asm volatile("ldmatrix.sync.aligned.m8n8.x4.shared.b16 {%0,%1,%2,%3}, [%4];"
                 : "=r"(r[0]), "=r"(r[1]), "=r"(r[2]), "=r"(r[3]) : "r"(addr));
}

__device__ __forceinline__ void ldsm4t(uint32_t r[4], uint32_t addr) {
    asm volatile("ldmatrix.sync.aligned.m8n8.x4.trans.shared.b16 {%0,%1,%2,%3}, [%4];"
                 : "=r"(r[0]), "=r"(r[1]), "=r"(r[2]), "=r"(r[3]) : "r"(addr));
}

__device__ __forceinline__ void mma_bf16(float c[4],
                                         uint32_t a0, uint32_t a1, uint32_t a2, uint32_t a3,
                                         uint32_t b0, uint32_t b1) {
    asm volatile("mma.sync.aligned.m16n8k16.row.col.f32.bf16.bf16.f32 "
                 "{%0,%1,%2,%3}, {%4,%5,%6,%7}, {%8,%9}, {%0,%1,%2,%3};"
                 : "+f"(c[0]), "+f"(c[1]), "+f"(c[2]), "+f"(c[3])
                 : "r"(a0), "r"(a1), "r"(a2), "r"(a3), "r"(b0), "r"(b1));
}

__global__ void __launch_bounds__(256, 2)
mothernet_mma(const float* __restrict__ x,    // [T, B, F]
              const float* __restrict__ w1,   // [B, F, H]
              const float* __restrict__ b1,   // [B, H]
              const float* __restrict__ w2,   // [B, H]
              const float* __restrict__ b2,   // [B]
              float* __restrict__ out)        // [T, B]
{
    // [buf][hi=0/lo=1][...]
    __shared__ __align__(16) uint16_t As[2][2][A_ELEMS];
    __shared__ __align__(16) uint16_t Bs[2][2][B_ELEMS];

    const int b    = blockIdx.y;
    const int t0   = blockIdx.x * TM;
    const int tid  = threadIdx.x;
    const int lane = tid & 31;
    const int wid  = tid >> 5;
    const int wm   = wid >> 2;          // 0..1 : m-slice of 64
    const int wn   = wid & 3;           // 0..3 : n-slice of 32
    const int m0w  = wm * 64;
    const int n0w  = wn * 32;
    const int gid  = lane >> 2;         // 0..7
    const int tig  = lane & 3;          // 0..3

    const float* xb  = x  + (size_t)t0 * (B_ * F_) + (size_t)b * F_;
    const float* w1b = w1 + (size_t)b * (F_ * H_);
    const float* b1b = b1 + b * H_;
    const float* w2b = w2 + b * H_;

    // gmem->smem loader mapping (256 threads, 8 floats each per tile)
    const int aRow = tid >> 2;          // 0..63  -> rows aRow, aRow+64
    const int aC4  = (tid & 3) * 4;     // k offset 0,4,8,12
    const int bRow = tid >> 5;          // 0..7   -> k rows bRow, bRow+8
    const int bC4  = (tid & 31) * 4;    // n offset 0..124

    // ldmatrix per-lane byte offsets
    const uint32_t a_base = smem_u32(&As[0][0][0]);
    const uint32_t b_base = smem_u32(&Bs[0][0][0]);
    // A: mat0 rows0-7 k0-7, mat1 rows8-15 k0-7, mat2 rows0-7 k8-15, mat3 rows8-15 k8-15
    const uint32_t aOff = (uint32_t)((m0w + (lane & 15)) * A_STRIDE + ((lane >> 4) * 8)) * 2u;
    // B(trans): mat0 (k0-7,n0-7), mat1 (k8-15,n0-7), mat2 (k0-7,n8-15), mat3 (k8-15,n8-15)
    const int kB = (lane & 7) + (((lane >> 3) & 1) * 8);
    const uint32_t bOff = (uint32_t)(kB * B_STRIDE + n0w + (((lane >> 4) & 1) * 8)) * 2u;

    float rowsum[8];
#pragma unroll
    for (int i = 0; i < 8; ++i) rowsum[i] = 0.0f;

    auto stash = [&](int buf, const float4& qa0, const float4& qa1,
                     const float4& qb0, const float4& qb1) {
        {   // A row aRow (nan -> 0 per reference)
            float v0 = fix_nan(qa0.x), v1 = fix_nan(qa0.y), v2 = fix_nan(qa0.z), v3 = fix_nan(qa0.w);
            float h0 = bfr(v0), h1 = bfr(v1), h2 = bfr(v2), h3 = bfr(v3);
            *(uint2*)&As[buf][0][aRow * A_STRIDE + aC4] = make_uint2(f2bf2(h0, h1), f2bf2(h2, h3));
            *(uint2*)&As[buf][1][aRow * A_STRIDE + aC4] =
                make_uint2(f2bf2(v0 - h0, v1 - h1), f2bf2(v2 - h2, v3 - h3));
        }
        {   // A row aRow + 64
            float v0 = fix_nan(qa1.x), v1 = fix_nan(qa1.y), v2 = fix_nan(qa1.z), v3 = fix_nan(qa1.w);
            float h0 = bfr(v0), h1 = bfr(v1), h2 = bfr(v2), h3 = bfr(v3);
            *(uint2*)&As[buf][0][(aRow + 64) * A_STRIDE + aC4] = make_uint2(f2bf2(h0, h1), f2bf2(h2, h3));
            *(uint2*)&As[buf][1][(aRow + 64) * A_STRIDE + aC4] =
                make_uint2(f2bf2(v0 - h0, v1 - h1), f2bf2(v2 - h2, v3 - h3));
        }
        {   // B k-row bRow
            float h0 = bfr(qb0.x), h1 = bfr(qb0.y), h2 = bfr(qb0.z), h3 = bfr(qb0.w);
            *(uint2*)&Bs[buf][0][bRow * B_STRIDE + bC4] = make_uint2(f2bf2(h0, h1), f2bf2(h2, h3));
            *(uint2*)&Bs[buf][1][bRow * B_STRIDE + bC4] =
                make_uint2(f2bf2(qb0.x - h0, qb0.y - h1), f2bf2(qb0.z - h2, qb0.w - h3));
        }
        {   // B k-row bRow + 8
            float h0 = bfr(qb1.x), h1 = bfr(qb1.y), h2 = bfr(qb1.z), h3 = bfr(qb1.w);
            *(uint2*)&Bs[buf][0][(bRow + 8) * B_STRIDE + bC4] = make_uint2(f2bf2(h0, h1), f2bf2(h2, h3));
            *(uint2*)&Bs[buf][1][(bRow + 8) * B_STRIDE + bC4] =
                make_uint2(f2bf2(qb1.x - h0, qb1.y - h1), f2bf2(qb1.z - h2, qb1.w - h3));
        }
    };

    const int NKT = F_ / TK;  // 32

    for (int hc = 0; hc < H_ / TN; ++hc) {
        const int h0 = hc * TN;

        float acc[4][4][4];
#pragma unroll
        for (int mt = 0; mt < 4; ++mt)
#pragma unroll
            for (int nt = 0; nt < 4; ++nt)
#pragma unroll
                for (int c = 0; c < 4; ++c) acc[mt][nt][c] = 0.0f;

        // prologue: chunk 0 -> buf 0
        float4 pa0 = *(const float4*)(xb + (size_t)aRow * (B_ * F_) + aC4);
        float4 pa1 = *(const float4*)(xb + (size_t)(aRow + 64) * (B_ * F_) + aC4);
        float4 pb0 = *(const float4*)(w1b + (size_t)bRow * H_ + h0 + bC4);
        float4 pb1 = *(const float4*)(w1b + (size_t)(bRow + 8) * H_ + h0 + bC4);
        stash(0, pa0, pa1, pb0, pb1);
        __syncthreads();

        for (int kt = 0; kt < NKT; ++kt) {
            const int buf = kt & 1;

            if (kt + 1 < NKT) {   // prefetch next chunk into registers
                const int k0 = (kt + 1) * TK;
                pa0 = *(const float4*)(xb + (size_t)aRow * (B_ * F_) + k0 + aC4);
                pa1 = *(const float4*)(xb + (size_t)(aRow + 64) * (B_ * F_) + k0 + aC4);
                pb0 = *(const float4*)(w1b + (size_t)(k0 + bRow) * H_ + h0 + bC4);
                pb1 = *(const float4*)(w1b + (size_t)(k0 + bRow + 8) * H_ + h0 + bC4);
            }

            // ---- fragments + 3-product split MMA ----
            uint32_t ah[4][4], al[4][4];
#pragma unroll
            for (int mt = 0; mt < 4; ++mt) {
                const uint32_t base = a_base + (uint32_t)buf * (2u * A_ELEMS * 2u)
                                    + aOff + (uint32_t)(mt * 16 * A_STRIDE) * 2u;
                ldsm4(ah[mt], base);
                ldsm4(al[mt], base + A_ELEMS * 2u);
            }
#pragma unroll
            for (int np = 0; np < 2; ++np) {
                uint32_t bh[4], bl[4];
                const uint32_t baseb = b_base + (uint32_t)buf * (2u * B_ELEMS * 2u)
                                     + bOff + (uint32_t)np * 32u;
                ldsm4t(bh, baseb);
                ldsm4t(bl, baseb + B_ELEMS * 2u);
#pragma unroll
                for (int half = 0; half < 2; ++half) {
                    const int nt = np * 2 + half;
                    const uint32_t bh0 = bh[half * 2], bh1 = bh[half * 2 + 1];
                    const uint32_t bl0 = bl[half * 2], bl1 = bl[half * 2 + 1];
#pragma unroll
                    for (int mt = 0; mt < 4; ++mt) {
                        mma_bf16(acc[mt][nt], ah[mt][0], ah[mt][1], ah[mt][2], ah[mt][3], bh0, bh1);
                        mma_bf16(acc[mt][nt], ah[mt][0], ah[mt][1], ah[mt][2], ah[mt][3], bl0, bl1);
                        mma_bf16(acc[mt][nt], al[mt][0], al[mt][1], al[mt][2], al[mt][3], bh0, bh1);
                    }
                }
            }

            if (kt + 1 < NKT) stash(buf ^ 1, pa0, pa1, pb0, pb1);
            __syncthreads();
        }

        // ---- fused epilogue: relu(acc + b1) * w2 -> rowsum ----
#pragma unroll
        for (int nt = 0; nt < 4; ++nt) {
            const int h = h0 + n0w + nt * 8 + tig * 2;
            const float bb0 = __ldg(b1b + h), bb1 = __ldg(b1b + h + 1);
            const float ww0 = __ldg(w2b + h), ww1 = __ldg(w2b + h + 1);
#pragma unroll
            for (int mt = 0; mt < 4; ++mt) {
                rowsum[mt * 2]     += fmaxf(acc[mt][nt][0] + bb0, 0.f) * ww0
                                    + fmaxf(acc[mt][nt][1] + bb1, 0.f) * ww1;
                rowsum[mt * 2 + 1] += fmaxf(acc[mt][nt][2] + bb0, 0.f) * ww0
                                    + fmaxf(acc[mt][nt][3] + bb1, 0.f) * ww1;
            }
        }
    }

    // ---- reduce over n: within warp (tig lanes), then across the 4 n-warps ----
#pragma unroll
    for (int i = 0; i < 8; ++i) {
        rowsum[i] += __shfl_xor_sync(0xffffffffu, rowsum[i], 1);
        rowsum[i] += __shfl_xor_sync(0xffffffffu, rowsum[i], 2);
    }

    float* red = (float*)&As[0][0][0];   // 128 rows x 4 n-warps = 2KB (reuse smem)
    if (tig == 0) {
#pragma unroll
        for (int mt = 0; mt < 4; ++mt) {
            red[(m0w + mt * 16 + gid) * 4 + wn]     = rowsum[mt * 2];
            red[(m0w + mt * 16 + gid + 8) * 4 + wn] = rowsum[mt * 2 + 1];
        }
    }
    __syncthreads();

    if (tid < TM) {
        float s = red[tid * 4] + red[tid * 4 + 1] + red[tid * 4 + 2] + red[tid * 4 + 3] + b2[b];
        out[(size_t)(t0 + tid) * B_ + b] = s;
    }
}

extern "C" void kernel_launch(void* const* d_in, const int* in_sizes, int n_in,
                              void* d_out, int out_size)
{
    (void)in_sizes; (void)n_in; (void)out_size;
    const float* x  = (const float*)d_in[0];
    const float* w1 = (const float*)d_in[1];
    const float* b1 = (const float*)d_in[2];
    const float* w2 = (const float*)d_in[3];
    const float* b2 = (const float*)d_in[4];
    float* out = (float*)d_out;

    dim3 grid(T_ / TM, B_);   // 32 x 8 = 256 CTAs, 2/SM -> one wave
    mothernet_mma<<<grid, 256>>>(x, w1, b1, w2, b2, out);
}